// round 8
// baseline (speedup 1.0000x reference)
#include <cuda_runtime.h>
#include <cuda_fp16.h>
#include <math.h>

#define NN 2592
#define BB 128
#define LL 64
#define CC 16
#define CHO 64

// ---------------- scratch (device globals; no allocation) ----------------
__device__ __half g_uhatH[(size_t)NN * BB * LL]; // [n][b][l]  ~42.5 MB fp16
__device__ float g_S0[BB * LL];                  // sum_n u_hat (exact fp32)
__device__ float g_s1[BB * LL];
__device__ float g_s2[BB * LL];
__device__ float g_b1[NN];
__device__ float g_b2[NN];
__device__ float g_c1[NN];
__device__ float g_c2[NN];
__device__ float g_nrm2[(size_t)NN * BB];        // [n][b] : sum_l u_hat^2 (exact fp32)

struct alignas(8) h4pack { __half2 a, b; };

__device__ __forceinline__ float squashf(float s) {
    float sq = s * s;
    return s * fabsf(s) / (1.0f + sq);   // == sq*s/((1+sq)*sqrt(sq))
}

__device__ __forceinline__ void red_add_v4(float* p, float a, float b, float c, float d) {
    asm volatile("red.global.add.v4.f32 [%0], {%1, %2, %3, %4};"
                 :: "l"(p), "f"(a), "f"(b), "f"(c), "f"(d) : "memory");
}

// 256-bit evict_last load (the only legal width for this hint on sm_100)
__device__ __forceinline__ void ldg_el_v8(const void* p, uint4& a, uint4& b) {
    asm("ld.global.L2::evict_last.v8.b32 {%0,%1,%2,%3,%4,%5,%6,%7}, [%8];"
        : "=r"(a.x), "=r"(a.y), "=r"(a.z), "=r"(a.w),
          "=r"(b.x), "=r"(b.y), "=r"(b.z), "=r"(b.w) : "l"(p));
}

// ---------------- K0: zero accumulators ----------------
__global__ void kzero() {
    int i = blockIdx.x * 256 + threadIdx.x;
    if (i < BB * LL) { g_S0[i] = 0.f; g_s1[i] = 0.f; g_s2[i] = 0.f; }
    if (i < NN) { g_b1[i] = 0.f; g_b2[i] = 0.f; }
}

// ---------------- K1: u_hat(fp16) + S0 (red.v4, fp32) + nrm2 (fp32) ----------------
// grid 648 (4 n per CTA), 256 threads. Per n: (128b x 64l) = x[:,n,:](128x16) @ W[n]^T(16x64)
__global__ void __launch_bounds__(256) k1_uhat(const float* __restrict__ x,
                                               const float* __restrict__ W) {
    __shared__ float xs[CC][BB];
    __shared__ float Ws[CC][LL];
    __shared__ float ps[CC][BB + 1];

    int t = threadIdx.x;
    int n0 = blockIdx.x * 4;
    int bg = t >> 4, lq = t & 15;
    int bbase = bg * 8;

    float s_acc[8][4];
#pragma unroll
    for (int i = 0; i < 8; i++)
#pragma unroll
        for (int j = 0; j < 4; j++) s_acc[i][j] = 0.f;

#pragma unroll 1
    for (int nn = 0; nn < 4; nn++) {
        int n = n0 + nn;
        {   // x[:, n, :] -> xs[c][b]
            int b = t & 127, half = t >> 7;
            const float4* xp = reinterpret_cast<const float4*>(x + ((size_t)b * NN + n) * CC) + half * 2;
            float4 a = xp[0], c4 = xp[1];
            int cb = half * 8;
            xs[cb + 0][b] = a.x;  xs[cb + 1][b] = a.y;  xs[cb + 2][b] = a.z;  xs[cb + 3][b] = a.w;
            xs[cb + 4][b] = c4.x; xs[cb + 5][b] = c4.y; xs[cb + 6][b] = c4.z; xs[cb + 7][b] = c4.w;
        }
        {   // W[n] -> Ws[c][l]
            int l = t & 63, cq = t >> 6;
            const float4* wp = reinterpret_cast<const float4*>(W + ((size_t)n * LL + l) * CC + cq * 4);
            float4 a = wp[0];
            Ws[cq * 4 + 0][l] = a.x; Ws[cq * 4 + 1][l] = a.y;
            Ws[cq * 4 + 2][l] = a.z; Ws[cq * 4 + 3][l] = a.w;
        }
        __syncthreads();

        float acc[8][4];
#pragma unroll
        for (int i = 0; i < 8; i++)
#pragma unroll
            for (int j = 0; j < 4; j++) acc[i][j] = 0.f;

#pragma unroll
        for (int c = 0; c < CC; c++) {
            float4 xa = *reinterpret_cast<const float4*>(&xs[c][bbase]);
            float4 xb = *reinterpret_cast<const float4*>(&xs[c][bbase + 4]);
            float4 wv = *reinterpret_cast<const float4*>(&Ws[c][lq * 4]);
            float xr[8] = {xa.x, xa.y, xa.z, xa.w, xb.x, xb.y, xb.z, xb.w};
            float wr[4] = {wv.x, wv.y, wv.z, wv.w};
#pragma unroll
            for (int i = 0; i < 8; i++)
#pragma unroll
                for (int j = 0; j < 4; j++) acc[i][j] += xr[i] * wr[j];
        }

        __half* ub = g_uhatH + (size_t)n * BB * LL;
#pragma unroll
        for (int i = 0; i < 8; i++) {
            int b = bbase + i;
            h4pack pk;
            pk.a = __floats2half2_rn(acc[i][0], acc[i][1]);
            pk.b = __floats2half2_rn(acc[i][2], acc[i][3]);
            *reinterpret_cast<h4pack*>(ub + b * LL + lq * 4) = pk;
            ps[lq][b] = acc[i][0] * acc[i][0] + acc[i][1] * acc[i][1] +
                        acc[i][2] * acc[i][2] + acc[i][3] * acc[i][3];
            s_acc[i][0] += acc[i][0]; s_acc[i][1] += acc[i][1];
            s_acc[i][2] += acc[i][2]; s_acc[i][3] += acc[i][3];
        }
        __syncthreads();
        if (t < BB) {
            float nr = 0.f;
#pragma unroll
            for (int q = 0; q < 16; q++) nr += ps[q][t];
            g_nrm2[(size_t)n * BB + t] = nr;
        }
        __syncthreads();
    }

#pragma unroll
    for (int i = 0; i < 8; i++)
        red_add_v4(&g_S0[(bbase + i) * LL + lq * 4],
                   s_acc[i][0], s_acc[i][1], s_acc[i][2], s_acc[i][3]);
}

// ---------------- a-pass ----------------
// b_out[n] += (1/B) * sum_{b in tile} <u_hat[b,n,:], v[b,:]>,  v = squash(sIn*scale)
// grid 1296 = 324 n-tiles (8 n) x 4 b-tiles (32 b). warp w handles n0+w over 32 b.
// Lane -> (row = lane>>2 of 8, seg = lane&3 of 16 halves); 4 row-passes, v8 loads.
__global__ void __launch_bounds__(256) k_apass(int mode) {
    const float* sIn = (mode == 0) ? g_S0 : g_s1;
    float sscale = (mode == 0) ? (1.0f / NN) : 1.0f;
    float* bOut = (mode == 0) ? g_b1 : g_b2;

    __shared__ float vs[32 * 68];   // padded rows (68) to avoid seg-major bank conflicts
    int t = threadIdx.x;
    int nt = blockIdx.x >> 2, bq = blockIdx.x & 3;
    int b0 = bq * 32;

    for (int i = t; i < 32 * LL; i += 256) {
        int row = i >> 6, l = i & 63;
        vs[row * 68 + l] = squashf(sIn[(b0 + row) * LL + l] * sscale);
    }
    __syncthreads();

    int w = t >> 5, lane = t & 31;
    int n = nt * 8 + w;
    int rg = lane >> 2, seg = lane & 3;
    float acc = 0.f;
#pragma unroll
    for (int p = 0; p < 4; p++) {
        int row = p * 8 + rg;                // b - b0
        const __half* up = g_uhatH + ((size_t)n * BB + b0 + row) * LL + seg * 16;
        uint4 qa, qb;
        ldg_el_v8(up, qa, qb);
        const float4* vrow = reinterpret_cast<const float4*>(vs + row * 68 + seg * 16);
        float4 v0 = vrow[0], v1 = vrow[1], v2 = vrow[2], v3 = vrow[3];
        float2 f;
        f = __half22float2(*reinterpret_cast<const __half2*>(&qa.x)); acc += f.x * v0.x + f.y * v0.y;
        f = __half22float2(*reinterpret_cast<const __half2*>(&qa.y)); acc += f.x * v0.z + f.y * v0.w;
        f = __half22float2(*reinterpret_cast<const __half2*>(&qa.z)); acc += f.x * v1.x + f.y * v1.y;
        f = __half22float2(*reinterpret_cast<const __half2*>(&qa.w)); acc += f.x * v1.z + f.y * v1.w;
        f = __half22float2(*reinterpret_cast<const __half2*>(&qb.x)); acc += f.x * v2.x + f.y * v2.y;
        f = __half22float2(*reinterpret_cast<const __half2*>(&qb.y)); acc += f.x * v2.z + f.y * v2.w;
        f = __half22float2(*reinterpret_cast<const __half2*>(&qb.z)); acc += f.x * v3.x + f.y * v3.y;
        f = __half22float2(*reinterpret_cast<const __half2*>(&qb.w)); acc += f.x * v3.z + f.y * v3.w;
    }
#pragma unroll
    for (int off = 16; off; off >>= 1) acc += __shfl_xor_sync(0xffffffffu, acc, off);
    if (lane == 0) {
        acc *= (1.0f / BB);
        if (mode == 1 && bq == 0) acc += g_b1[n];   // b2 = b1 + mean
        atomicAdd(&bOut[n], acc);
    }
}

// ---------------- k_soft: c = softmax(bIn) once, globally ----------------
__global__ void __launch_bounds__(1024) k_soft(int mode) {
    const float* bIn = (mode == 0) ? g_b1 : g_b2;
    float* cOut = (mode == 0) ? g_c1 : g_c2;

    __shared__ float wred[32];
    __shared__ float bc;
    int t = threadIdx.x, lane = t & 31, wid = t >> 5;

    float va = (t < NN) ? bIn[t] : -3.0e38f;
    float vb = (t + 1024 < NN) ? bIn[t + 1024] : -3.0e38f;
    float vc = (t + 2048 < NN) ? bIn[t + 2048] : -3.0e38f;

    float m = fmaxf(va, fmaxf(vb, vc));
#pragma unroll
    for (int off = 16; off; off >>= 1) m = fmaxf(m, __shfl_xor_sync(0xffffffffu, m, off));
    if (lane == 0) wred[wid] = m;
    __syncthreads();
    if (wid == 0) {
        float mm = wred[lane];
#pragma unroll
        for (int off = 16; off; off >>= 1) mm = fmaxf(mm, __shfl_xor_sync(0xffffffffu, mm, off));
        if (lane == 0) bc = mm;
    }
    __syncthreads();
    float mx = bc;

    float ea = __expf(va - mx);
    float eb = (t + 1024 < NN) ? __expf(vb - mx) : 0.f;
    float ec = (t + 2048 < NN) ? __expf(vc - mx) : 0.f;
    float sm = ea + eb + ec;
#pragma unroll
    for (int off = 16; off; off >>= 1) sm += __shfl_xor_sync(0xffffffffu, sm, off);
    if (lane == 0) wred[wid] = sm;
    __syncthreads();
    if (wid == 0) {
        float ss = wred[lane];
#pragma unroll
        for (int off = 16; off; off >>= 1) ss += __shfl_xor_sync(0xffffffffu, ss, off);
        if (lane == 0) bc = ss;
    }
    __syncthreads();
    float inv = 1.0f / bc;

    if (t < NN) cOut[t] = ea * inv;
    if (t + 1024 < NN) cOut[t + 1024] = eb * inv;
    if (t + 2048 < NN) cOut[t + 2048] = ec * inv;
}

// ---------------- s-pass ----------------
// sOut[b,l] += sum_{n in tile} c[n]*u_hat[n,b,l]; c precomputed by k_soft.
// grid 1296 = 324 n-tiles (8 n) x 4 b-tiles (32 b).
// Thread -> (ngrp = t>>7 covering 4 n, row = (t&127)>>2, seg = t&3 of 16 halves).
__global__ void __launch_bounds__(256) k_spass(int mode) {
    const float* cIn = (mode == 0) ? g_c1 : g_c2;
    float* sOut = (mode == 0) ? g_s1 : g_s2;

    __shared__ float cs[8];
    int t = threadIdx.x;
    int nt = blockIdx.x >> 2, bq = blockIdx.x & 3;
    int n0 = nt * 8, b0 = bq * 32;

    if (t < 8) cs[t] = cIn[n0 + t];
    __syncthreads();

    int ngrp = t >> 7, c = t & 127;
    int bl = c >> 2, seg = c & 3;
    float a[16];
#pragma unroll
    for (int k = 0; k < 16; k++) a[k] = 0.f;

#pragma unroll
    for (int i = 0; i < 4; i++) {
        int nn = ngrp * 4 + i;
        float cv = cs[nn];
        const __half* p = g_uhatH + ((size_t)(n0 + nn) * BB + b0 + bl) * LL + seg * 16;
        uint4 qa, qb;
        ldg_el_v8(p, qa, qb);
        float2 f;
        f = __half22float2(*reinterpret_cast<const __half2*>(&qa.x)); a[0] += cv * f.x; a[1] += cv * f.y;
        f = __half22float2(*reinterpret_cast<const __half2*>(&qa.y)); a[2] += cv * f.x; a[3] += cv * f.y;
        f = __half22float2(*reinterpret_cast<const __half2*>(&qa.z)); a[4] += cv * f.x; a[5] += cv * f.y;
        f = __half22float2(*reinterpret_cast<const __half2*>(&qa.w)); a[6] += cv * f.x; a[7] += cv * f.y;
        f = __half22float2(*reinterpret_cast<const __half2*>(&qb.x)); a[8] += cv * f.x; a[9] += cv * f.y;
        f = __half22float2(*reinterpret_cast<const __half2*>(&qb.y)); a[10] += cv * f.x; a[11] += cv * f.y;
        f = __half22float2(*reinterpret_cast<const __half2*>(&qb.z)); a[12] += cv * f.x; a[13] += cv * f.y;
        f = __half22float2(*reinterpret_cast<const __half2*>(&qb.w)); a[14] += cv * f.x; a[15] += cv * f.y;
    }
    float* dst = sOut + (b0 + bl) * LL + seg * 16;
    red_add_v4(dst,      a[0],  a[1],  a[2],  a[3]);
    red_add_v4(dst + 4,  a[4],  a[5],  a[6],  a[7]);
    red_add_v4(dst + 8,  a[8],  a[9],  a[10], a[11]);
    red_add_v4(dst + 12, a[12], a[13], a[14], a[15]);
}

// ---------------- K6: v_j output + ConvTranspose2d ----------------
__global__ void __launch_bounds__(256) k6_out(const float* __restrict__ cw,
                                              const float* __restrict__ cb,
                                              float* __restrict__ out) {
    int t = threadIdx.x;
    if (blockIdx.x >= 2048) {
        int idx = (blockIdx.x - 2048) * 256 + t;   // 32*256 = 8192
        out[idx] = squashf(g_s2[idx]);
        return;
    }
    int b = blockIdx.x >> 4, oh = blockIdx.x & 15;
    __shared__ float ws[32][64][2];
    __shared__ float un[32][9];
    __shared__ float bias[CHO];

    int kh = oh & 1;
    int ih = (oh + kh) >> 1;

    for (int i = t; i < 32 * 64 * 2; i += 256) {
        int ic = i >> 7, r = i & 127, oc = r >> 1, j = r & 1;
        ws[ic][oc][j] = cw[ic * 256 + oc * 4 + (1 - kh) * 2 + j];
    }
    for (int i = t; i < 288; i += 256) {
        int ic = i / 9, iw = i - ic * 9;
        int n = ic * 81 + ih * 9 + iw;
        un[ic][iw] = g_c2[n] * sqrtf(g_nrm2[(size_t)n * BB + b]);
    }
    if (t < CHO) bias[t] = cb[t];
    __syncthreads();

    int ow = t & 15, ocg = t >> 4;
    int kw = ow & 1;
    int iw = (ow + kw) >> 1;
    int j = 1 - kw;
    size_t obase = 8192 + (((size_t)b * CHO) * 16 + oh) * 16 + ow;
#pragma unroll
    for (int q = 0; q < 4; q++) {
        int oc = ocg * 4 + q;
        float acc = bias[oc];
#pragma unroll
        for (int ic = 0; ic < 32; ic++) acc += un[ic][iw] * ws[ic][oc][j];
        out[obase + (size_t)oc * 256] = acc;
    }
}

// ---------------- launch ----------------
extern "C" void kernel_launch(void* const* d_in, const int* in_sizes, int n_in,
                              void* d_out, int out_size) {
    const float* x  = (const float*)d_in[0];   // (128, 2592, 16)
    const float* W  = (const float*)d_in[1];   // (1, 2592, 1, 64, 16)
    const float* cw = (const float*)d_in[2];   // (32, 64, 2, 2)
    const float* cb = (const float*)d_in[3];   // (64,)
    float* out = (float*)d_out;                // 8192 (v_j) + 2097152 (out_img)

    kzero<<<32, 256>>>();
    k1_uhat<<<648, 256>>>(x, W);    // u_hat(fp16) + S0 + nrm2
    k_apass<<<1296, 256>>>(0);      // v0=squash(S0/N); b1 = mean_b <u_hat, v0>
    k_soft<<<1, 1024>>>(0);         // c1 = softmax(b1)
    k_spass<<<1296, 256>>>(0);      // s1 = sum c1*u_hat
    k_apass<<<1296, 256>>>(1);      // v1=squash(s1);  b2 = b1 + mean_b <u_hat, v1>
    k_soft<<<1, 1024>>>(1);         // c2 = softmax(b2)
    k_spass<<<1296, 256>>>(1);      // s2 = sum c2*u_hat
    k6_out<<<2080, 256>>>(cw, cb, out);  // v_j = squash(s2); ConvT -> out_img
}

// round 10
// speedup vs baseline: 1.1428x; 1.1428x over previous
#include <cuda_runtime.h>
#include <cuda_fp16.h>
#include <math.h>

#define NN 2592
#define BB 128
#define LL 64
#define CC 16
#define CHO 64

// ---------------- scratch (device globals; no allocation) ----------------
__device__ __half g_uhatH[(size_t)NN * BB * LL]; // [n][b][l]  ~42.5 MB fp16
__device__ float g_S0[BB * LL];                  // sum_n u_hat (exact fp32)
__device__ float g_s1[BB * LL];
__device__ float g_s2[BB * LL];
__device__ float g_b1[NN];
__device__ float g_b2[NN];
__device__ float g_c1[NN];
__device__ float g_c2[NN];
__device__ float g_nrm2[(size_t)NN * BB];        // [n][b] : sum_l u_hat^2 (exact fp32)
__device__ unsigned g_cnt[2];                    // a-pass completion tickets

struct alignas(8) h4pack { __half2 a, b; };

__device__ __forceinline__ float squashf(float s) {
    float sq = s * s;
    return s * fabsf(s) / (1.0f + sq);   // == sq*s/((1+sq)*sqrt(sq))
}

__device__ __forceinline__ void red_add_v4(float* p, float a, float b, float c, float d) {
    asm volatile("red.global.add.v4.f32 [%0], {%1, %2, %3, %4};"
                 :: "l"(p), "f"(a), "f"(b), "f"(c), "f"(d) : "memory");
}

// ---------------- K0: zero accumulators ----------------
__global__ void kzero() {
    int i = blockIdx.x * 256 + threadIdx.x;
    if (i < BB * LL) { g_S0[i] = 0.f; g_s1[i] = 0.f; g_s2[i] = 0.f; }
    if (i < NN) { g_b1[i] = 0.f; g_b2[i] = 0.f; }
    if (i < 2) g_cnt[i] = 0u;
}

// ---------------- K1: u_hat(fp16) + S0 (red.v4, fp32) + nrm2 (fp32) ----------------
// grid 648 (4 n per CTA), 256 threads. Per n: (128b x 64l) = x[:,n,:](128x16) @ W[n]^T(16x64)
__global__ void __launch_bounds__(256) k1_uhat(const float* __restrict__ x,
                                               const float* __restrict__ W) {
    __shared__ float xs[CC][BB];
    __shared__ float Ws[CC][LL];
    __shared__ float ps[CC][BB + 1];

    int t = threadIdx.x;
    int n0 = blockIdx.x * 4;
    int bg = t >> 4, lq = t & 15;
    int bbase = bg * 8;

    float s_acc[8][4];
#pragma unroll
    for (int i = 0; i < 8; i++)
#pragma unroll
        for (int j = 0; j < 4; j++) s_acc[i][j] = 0.f;

#pragma unroll 1
    for (int nn = 0; nn < 4; nn++) {
        int n = n0 + nn;
        {   // x[:, n, :] -> xs[c][b]
            int b = t & 127, half = t >> 7;
            const float4* xp = reinterpret_cast<const float4*>(x + ((size_t)b * NN + n) * CC) + half * 2;
            float4 a = xp[0], c4 = xp[1];
            int cb = half * 8;
            xs[cb + 0][b] = a.x;  xs[cb + 1][b] = a.y;  xs[cb + 2][b] = a.z;  xs[cb + 3][b] = a.w;
            xs[cb + 4][b] = c4.x; xs[cb + 5][b] = c4.y; xs[cb + 6][b] = c4.z; xs[cb + 7][b] = c4.w;
        }
        {   // W[n] -> Ws[c][l]
            int l = t & 63, cq = t >> 6;
            const float4* wp = reinterpret_cast<const float4*>(W + ((size_t)n * LL + l) * CC + cq * 4);
            float4 a = wp[0];
            Ws[cq * 4 + 0][l] = a.x; Ws[cq * 4 + 1][l] = a.y;
            Ws[cq * 4 + 2][l] = a.z; Ws[cq * 4 + 3][l] = a.w;
        }
        __syncthreads();

        float acc[8][4];
#pragma unroll
        for (int i = 0; i < 8; i++)
#pragma unroll
            for (int j = 0; j < 4; j++) acc[i][j] = 0.f;

#pragma unroll
        for (int c = 0; c < CC; c++) {
            float4 xa = *reinterpret_cast<const float4*>(&xs[c][bbase]);
            float4 xb = *reinterpret_cast<const float4*>(&xs[c][bbase + 4]);
            float4 wv = *reinterpret_cast<const float4*>(&Ws[c][lq * 4]);
            float xr[8] = {xa.x, xa.y, xa.z, xa.w, xb.x, xb.y, xb.z, xb.w};
            float wr[4] = {wv.x, wv.y, wv.z, wv.w};
#pragma unroll
            for (int i = 0; i < 8; i++)
#pragma unroll
                for (int j = 0; j < 4; j++) acc[i][j] += xr[i] * wr[j];
        }

        __half* ub = g_uhatH + (size_t)n * BB * LL;
#pragma unroll
        for (int i = 0; i < 8; i++) {
            int b = bbase + i;
            h4pack pk;
            pk.a = __floats2half2_rn(acc[i][0], acc[i][1]);
            pk.b = __floats2half2_rn(acc[i][2], acc[i][3]);
            *reinterpret_cast<h4pack*>(ub + b * LL + lq * 4) = pk;
            ps[lq][b] = acc[i][0] * acc[i][0] + acc[i][1] * acc[i][1] +
                        acc[i][2] * acc[i][2] + acc[i][3] * acc[i][3];
            s_acc[i][0] += acc[i][0]; s_acc[i][1] += acc[i][1];
            s_acc[i][2] += acc[i][2]; s_acc[i][3] += acc[i][3];
        }
        __syncthreads();
        if (t < BB) {
            float nr = 0.f;
#pragma unroll
            for (int q = 0; q < 16; q++) nr += ps[q][t];
            g_nrm2[(size_t)n * BB + t] = nr;
        }
        __syncthreads();
    }

#pragma unroll
    for (int i = 0; i < 8; i++)
        red_add_v4(&g_S0[(bbase + i) * LL + lq * 4],
                   s_acc[i][0], s_acc[i][1], s_acc[i][2], s_acc[i][3]);
}

// ---------------- a-pass (+ fused last-CTA softmax) ----------------
// b_out[n] += (1/B) * sum_{b in tile} <u_hat[b,n,:], v[b,:]>,  v = squash(sIn*scale)
// grid 1296 = 324 n-tiles (8 n) x 4 b-tiles (32 b).
// Thread -> (row = t>>3 of 32 b, seg = t&7 of 8 uint4); 8 n-deep MLP.
// The CTA drawing the last ticket computes c = softmax(b_out) inline.
__global__ void __launch_bounds__(256) k_apass(int mode) {
    const float* sIn = (mode == 0) ? g_S0 : g_s1;
    float sscale = (mode == 0) ? (1.0f / NN) : 1.0f;
    float* bOut = (mode == 0) ? g_b1 : g_b2;
    float* cOut = (mode == 0) ? g_c1 : g_c2;

    __shared__ float vs[32 * 68];    // padded rows
    __shared__ float wsum[8][8];     // [warp][n]
    __shared__ float s8[8];
    __shared__ unsigned s_tk;
    __shared__ float sred[8];

    int t = threadIdx.x;
    int lane = t & 31, wid = t >> 5;
    int nt = blockIdx.x >> 2, bq = blockIdx.x & 3;
    int n0 = nt * 8, b0 = bq * 32;

    for (int i = t; i < 32 * LL; i += 256) {
        int row = i >> 6, l = i & 63;
        vs[row * 68 + l] = squashf(sIn[(b0 + row) * LL + l] * sscale);
    }
    __syncthreads();

    int row = t >> 3, seg = t & 7;
    const uint4* base = reinterpret_cast<const uint4*>(
        g_uhatH + ((size_t)n0 * BB + b0 + row) * LL) + seg;
    const float4* vrow = reinterpret_cast<const float4*>(vs + row * 68 + seg * 8);
    float4 v0 = vrow[0], v1 = vrow[1];

    float acc[8];
#pragma unroll
    for (int nn = 0; nn < 8; nn++) {
        uint4 q = base[nn * (BB * LL / 8)];
        float2 f0 = __half22float2(*reinterpret_cast<const __half2*>(&q.x));
        float2 f1 = __half22float2(*reinterpret_cast<const __half2*>(&q.y));
        float2 f2 = __half22float2(*reinterpret_cast<const __half2*>(&q.z));
        float2 f3 = __half22float2(*reinterpret_cast<const __half2*>(&q.w));
        acc[nn] = f0.x * v0.x + f0.y * v0.y + f1.x * v0.z + f1.y * v0.w +
                  f2.x * v1.x + f2.y * v1.y + f3.x * v1.z + f3.y * v1.w;
    }
#pragma unroll
    for (int nn = 0; nn < 8; nn++) {
#pragma unroll
        for (int off = 16; off; off >>= 1)
            acc[nn] += __shfl_xor_sync(0xffffffffu, acc[nn], off);
    }
    if (lane == 0) {
#pragma unroll
        for (int nn = 0; nn < 8; nn++) wsum[wid][nn] = acc[nn];
    }
    __syncthreads();
    if (t < 8) {
        float sum = wsum[0][t] + wsum[1][t] + wsum[2][t] + wsum[3][t] +
                    wsum[4][t] + wsum[5][t] + wsum[6][t] + wsum[7][t];
        sum *= (1.0f / BB);
        if (mode == 1 && bq == 0) sum += g_b1[n0 + t];   // b2 = b1 + mean
        s8[t] = sum;
    }
    __syncthreads();

    if (t == 0) {
#pragma unroll
        for (int i = 0; i < 8; i++) atomicAdd(&bOut[n0 + i], s8[i]);
        __threadfence();
        s_tk = atomicAdd(&g_cnt[mode], 1u);
    }
    __syncthreads();
    if (s_tk != 1295u) return;

    // ---- last CTA: softmax over bOut -> cOut (256 threads) ----
    __threadfence();   // acquire: see all CTAs' bOut atomics
    float m = -3.0e38f;
    for (int i = t; i < NN; i += 256) m = fmaxf(m, bOut[i]);
#pragma unroll
    for (int off = 16; off; off >>= 1) m = fmaxf(m, __shfl_xor_sync(0xffffffffu, m, off));
    if (lane == 0) sred[wid] = m;
    __syncthreads();
    float mx = sred[0];
#pragma unroll
    for (int q = 1; q < 8; q++) mx = fmaxf(mx, sred[q]);
    __syncthreads();

    float sm = 0.f;
    for (int i = t; i < NN; i += 256) sm += __expf(bOut[i] - mx);
#pragma unroll
    for (int off = 16; off; off >>= 1) sm += __shfl_xor_sync(0xffffffffu, sm, off);
    if (lane == 0) sred[wid] = sm;
    __syncthreads();
    float inv = 1.0f / (sred[0] + sred[1] + sred[2] + sred[3] +
                        sred[4] + sred[5] + sred[6] + sred[7]);
    for (int i = t; i < NN; i += 256) cOut[i] = __expf(bOut[i] - mx) * inv;
}

// ---------------- s-pass ----------------
// sOut[b,l] += sum_{n in tile} c[n]*u_hat[n,b,l]; c precomputed in a-pass tail.
// grid 1296 = 324 n-tiles (8 n) x 4 b-tiles (32 b).
__global__ void __launch_bounds__(256) k_spass(int mode) {
    const float* cIn = (mode == 0) ? g_c1 : g_c2;
    float* sOut = (mode == 0) ? g_s1 : g_s2;

    __shared__ float cs[8];
    int t = threadIdx.x;
    int nt = blockIdx.x >> 2, bq = blockIdx.x & 3;
    int n0 = nt * 8, b0 = bq * 32;

    if (t < 8) cs[t] = cIn[n0 + t];
    __syncthreads();

    // thread -> (bl = t>>3 in [0,32), l4 = t&7): one uint4 (8 fp16) per n
    int bl = t >> 3, l4 = t & 7;
    float a0 = 0.f, a1 = 0.f, a2 = 0.f, a3 = 0.f;
    float a4 = 0.f, a5 = 0.f, a6 = 0.f, a7 = 0.f;
#pragma unroll
    for (int nn = 0; nn < 8; nn++) {
        float cv = cs[nn];
        const uint4* p = reinterpret_cast<const uint4*>(
            g_uhatH + ((size_t)(n0 + nn) * BB + b0 + bl) * LL);
        uint4 q = p[l4];
        float2 f0 = __half22float2(*reinterpret_cast<const __half2*>(&q.x));
        float2 f1 = __half22float2(*reinterpret_cast<const __half2*>(&q.y));
        float2 f2 = __half22float2(*reinterpret_cast<const __half2*>(&q.z));
        float2 f3 = __half22float2(*reinterpret_cast<const __half2*>(&q.w));
        a0 += cv * f0.x; a1 += cv * f0.y; a2 += cv * f1.x; a3 += cv * f1.y;
        a4 += cv * f2.x; a5 += cv * f2.y; a6 += cv * f3.x; a7 += cv * f3.y;
    }
    float* dst = sOut + (b0 + bl) * LL + l4 * 8;
    red_add_v4(dst, a0, a1, a2, a3);
    red_add_v4(dst + 4, a4, a5, a6, a7);
}

// ---------------- K6: v_j output + ConvTranspose2d ----------------
__global__ void __launch_bounds__(256) k6_out(const float* __restrict__ cw,
                                              const float* __restrict__ cb,
                                              float* __restrict__ out) {
    int t = threadIdx.x;
    if (blockIdx.x >= 2048) {
        int idx = (blockIdx.x - 2048) * 256 + t;   // 32*256 = 8192
        out[idx] = squashf(g_s2[idx]);
        return;
    }
    int b = blockIdx.x >> 4, oh = blockIdx.x & 15;
    __shared__ float ws[32][64][2];
    __shared__ float un[32][9];
    __shared__ float bias[CHO];

    int kh = oh & 1;
    int ih = (oh + kh) >> 1;

    for (int i = t; i < 32 * 64 * 2; i += 256) {
        int ic = i >> 7, r = i & 127, oc = r >> 1, j = r & 1;
        ws[ic][oc][j] = cw[ic * 256 + oc * 4 + (1 - kh) * 2 + j];
    }
    for (int i = t; i < 288; i += 256) {
        int ic = i / 9, iw = i - ic * 9;
        int n = ic * 81 + ih * 9 + iw;
        un[ic][iw] = g_c2[n] * sqrtf(g_nrm2[(size_t)n * BB + b]);
    }
    if (t < CHO) bias[t] = cb[t];
    __syncthreads();

    int ow = t & 15, ocg = t >> 4;
    int kw = ow & 1;
    int iw = (ow + kw) >> 1;
    int j = 1 - kw;
    size_t obase = 8192 + (((size_t)b * CHO) * 16 + oh) * 16 + ow;
#pragma unroll
    for (int q = 0; q < 4; q++) {
        int oc = ocg * 4 + q;
        float acc = bias[oc];
#pragma unroll
        for (int ic = 0; ic < 32; ic++) acc += un[ic][iw] * ws[ic][oc][j];
        out[obase + (size_t)oc * 256] = acc;
    }
}

// ---------------- launch ----------------
extern "C" void kernel_launch(void* const* d_in, const int* in_sizes, int n_in,
                              void* d_out, int out_size) {
    const float* x  = (const float*)d_in[0];   // (128, 2592, 16)
    const float* W  = (const float*)d_in[1];   // (1, 2592, 1, 64, 16)
    const float* cw = (const float*)d_in[2];   // (32, 64, 2, 2)
    const float* cb = (const float*)d_in[3];   // (64,)
    float* out = (float*)d_out;                // 8192 (v_j) + 2097152 (out_img)

    kzero<<<32, 256>>>();
    k1_uhat<<<648, 256>>>(x, W);    // u_hat(fp16) + S0 + nrm2
    k_apass<<<1296, 256>>>(0);      // b1 = mean_b <u_hat, squash(S0/N)>; tail: c1=softmax(b1)
    k_spass<<<1296, 256>>>(0);      // s1 = sum c1*u_hat
    k_apass<<<1296, 256>>>(1);      // b2 = b1 + mean_b <u_hat, squash(s1)>; tail: c2=softmax(b2)
    k_spass<<<1296, 256>>>(1);      // s2 = sum c2*u_hat
    k6_out<<<2080, 256>>>(cw, cb, out);  // v_j = squash(s2); ConvT -> out_img
}